// round 16
// baseline (speedup 1.0000x reference)
#include <cuda_runtime.h>
#include <cuda_fp16.h>
#include <math.h>
#include <stdint.h>

// ---------------- problem constants ----------------
#define BATCH 2
#define SEQ   2048
#define DM    1024
#define NH    16
#define DH    64
#define NTOK  (BATCH*SEQ)        // 4096
#define CHUNK 128
#define NCH   (SEQ/CHUNK)        // 16
#define NBH   (BATCH*NH)         // 32

// ---------------- scratch (device globals; no allocs allowed) ----------------
__device__ __half  g_xnorm_h[NTOK*DM];
__device__ __half  g_xr_h   [NTOK*DM];
__device__ __half  g_qkv_h  [NTOK*3*DM];
__device__ __half  g_gate_h [NTOK*DM];
__device__ __half  g_qh_h   [NBH*SEQ*DH];
__device__ __half  g_kh_h   [NBH*SEQ*DH];
__device__ __half  g_vh_h   [NBH*SEQ*DH];
__device__ float   g_kv     [NBH*NCH*DH*DH];   // per chunk: [m][d]
__device__ float   g_kvpre  [NBH*NCH*DH*DH];   // [m][d]
__device__ float   g_ksum   [NBH*NCH*DH];
__device__ float   g_kspre  [NBH*NCH*DH];
__device__ __half  g_ctx_h  [NTOK*DM];
__device__ __half  g_wqkv_h [(3*DM)*DM];   // [n][k] fp16 (transposed)
__device__ __half  g_wgate_h[DM*DM];       // [n][k]
__device__ __half  g_wproj_h[DM*DM];       // [n][k]

// ---------------- helpers ----------------
__device__ __forceinline__ void mma_f16(float* c, const uint32_t* a, const uint32_t* b) {
    asm volatile(
        "mma.sync.aligned.m16n8k16.row.col.f32.f16.f16.f32 "
        "{%0,%1,%2,%3}, {%4,%5,%6,%7}, {%8,%9}, {%0,%1,%2,%3};"
        : "+f"(c[0]), "+f"(c[1]), "+f"(c[2]), "+f"(c[3])
        : "r"(a[0]), "r"(a[1]), "r"(a[2]), "r"(a[3]), "r"(b[0]), "r"(b[1]));
}
__device__ __forceinline__ void ldsm_x4(uint32_t* r, uint32_t addr) {
    asm volatile("ldmatrix.sync.aligned.m8n8.x4.shared.b16 {%0,%1,%2,%3}, [%4];"
        : "=r"(r[0]), "=r"(r[1]), "=r"(r[2]), "=r"(r[3]) : "r"(addr));
}
__device__ __forceinline__ void ldsm_x2(uint32_t* r, uint32_t addr) {
    asm volatile("ldmatrix.sync.aligned.m8n8.x2.shared.b16 {%0,%1}, [%2];"
        : "=r"(r[0]), "=r"(r[1]) : "r"(addr));
}
__device__ __forceinline__ uint32_t smem_u32(const void* p) {
    uint32_t a;
    asm("{ .reg .u64 t; cvta.to.shared.u64 t, %1; cvt.u32.u64 %0, t; }" : "=r"(a) : "l"(p));
    return a;
}
__device__ __forceinline__ void cp16(uint32_t dst, const void* src) {
    asm volatile("cp.async.cg.shared.global [%0], [%1], 16;" :: "r"(dst), "l"(src));
}
#define CP_COMMIT() asm volatile("cp.async.commit_group;" ::: "memory")
#define CP_WAIT(n)  asm volatile("cp.async.wait_group %0;" :: "n"(n) : "memory")

// ================= fp16 mma.sync GEMM core: BK=64 =================
#define ROW_H 72
#define ASTB (128*ROW_H*2)
#define BSTB (128*ROW_H*2)
#define GEMM_SMEM_BYTES (3*(ASTB+BSTB))  // 110592
#define NKT (DM/64)

template<bool SIGMOID, bool HALF_OUT>
__device__ __forceinline__ void gemm_tile(
    const __half* __restrict__ A, const __half* __restrict__ B,
    const float* __restrict__ bias, void* __restrict__ Cv,
    int N, int bm0, int bn0, char* sm) {

    uint32_t sA = smem_u32(sm);
    uint32_t sB = sA + 3 * ASTB;
    int tid = threadIdx.x;
    int wid = tid >> 5, lane = tid & 31;
    int gid = lane >> 2, tig = lane & 3;
    int wm = (wid & 1) * 64, wn = (wid >> 1) * 64;

    float c[4][8][4];
    #pragma unroll
    for (int mf = 0; mf < 4; mf++)
        #pragma unroll
        for (int nf = 0; nf < 8; nf++)
            #pragma unroll
            for (int r = 0; r < 4; r++) c[mf][nf][r] = 0.f;

    auto stage = [&](int s, int kt) {
        const __half* Ab = A + (size_t)bm0 * DM + kt * 64;
        const __half* Bb = B + (size_t)bn0 * DM + kt * 64;
        uint32_t sAb = sA + s * ASTB;
        uint32_t sBb = sB + s * BSTB;
        #pragma unroll
        for (int l = 0; l < 8; l++) {
            int id = tid + l * 128;
            int r  = id >> 3, ch = id & 7;
            cp16(sAb + r * (ROW_H * 2) + ch * 16, Ab + (size_t)r * DM + ch * 8);
            cp16(sBb + r * (ROW_H * 2) + ch * 16, Bb + (size_t)r * DM + ch * 8);
        }
    };

    uint32_t aOff = (uint32_t)(((wm + (lane & 15)) * ROW_H + (lane >> 4) * 8) * 2);
    uint32_t bOff = (uint32_t)(((wn + (lane & 7)) * ROW_H + ((lane >> 3) & 1) * 8) * 2);

    stage(0, 0); CP_COMMIT();
    stage(1, 1); CP_COMMIT();

    for (int kt = 0; kt < NKT; kt++) {
        if (kt + 1 < NKT) { CP_WAIT(1); } else { CP_WAIT(0); }
        __syncthreads();

        int buf = kt % 3;
        uint32_t aBase = sA + buf * ASTB + aOff;
        uint32_t bBase = sB + buf * BSTB + bOff;
        #pragma unroll
        for (int ks = 0; ks < 4; ks++) {
            uint32_t a[4][4], b[8][2];
            #pragma unroll
            for (int mf = 0; mf < 4; mf++)
                ldsm_x4(a[mf], aBase + (mf * 16 * ROW_H + ks * 16) * 2);
            #pragma unroll
            for (int nf = 0; nf < 8; nf++)
                ldsm_x2(b[nf], bBase + (nf * 8 * ROW_H + ks * 16) * 2);
            #pragma unroll
            for (int mf = 0; mf < 4; mf++)
                #pragma unroll
                for (int nf = 0; nf < 8; nf++)
                    mma_f16(c[mf][nf], a[mf], b[nf]);
        }

        if (kt + 2 < NKT) { stage((kt + 2) % 3, kt + 2); CP_COMMIT(); }
    }

    #pragma unroll
    for (int mf = 0; mf < 4; mf++) {
        int row = bm0 + wm + mf * 16 + gid;
        #pragma unroll
        for (int nf = 0; nf < 8; nf++) {
            int col = bn0 + wn + nf * 8 + tig * 2;
            float b0 = bias[col], b1 = bias[col + 1];
            float2 o0 = make_float2(c[mf][nf][0] + b0, c[mf][nf][1] + b1);
            float2 o1 = make_float2(c[mf][nf][2] + b0, c[mf][nf][3] + b1);
            if (SIGMOID) {
                o0.x = 1.f / (1.f + expf(-o0.x)); o0.y = 1.f / (1.f + expf(-o0.y));
                o1.x = 1.f / (1.f + expf(-o1.x)); o1.y = 1.f / (1.f + expf(-o1.y));
            }
            if (HALF_OUT) {
                __half* C = (__half*)Cv;
                *(__half2*)(C + (size_t)row * N + col)       = __floats2half2_rn(o0.x, o0.y);
                *(__half2*)(C + (size_t)(row + 8) * N + col) = __floats2half2_rn(o1.x, o1.y);
            } else {
                float* C = (float*)Cv;
                *(float2*)(C + (size_t)row * N + col) = o0;
                *(float2*)(C + (size_t)(row + 8) * N + col) = o1;
            }
        }
    }
}

#define QKV_TILES 768
#define ALL_TILES (QKV_TILES + 256)

__global__ void __launch_bounds__(128, 2)
mma_gemm_dual(const __half* __restrict__ Aq, const __half* __restrict__ Bq,
              const float* __restrict__ biasq,
              const __half* __restrict__ Ag, const __half* __restrict__ Bg,
              const float* __restrict__ biasg) {
    extern __shared__ char smc[];
    for (int it = blockIdx.x; it < ALL_TILES; it += gridDim.x) {
        __syncthreads();
        if (it < QKV_TILES) {
            int bm = it / 24, bn = it % 24;
            gemm_tile<false, true>(Aq, Bq, biasq, g_qkv_h, 3 * DM, bm * 128, bn * 128, smc);
        } else {
            int t2 = it - QKV_TILES;
            int bm = t2 / 8, bn = t2 % 8;
            gemm_tile<true, true>(Ag, Bg, biasg, g_gate_h, DM, bm * 128, bn * 128, smc);
        }
    }
}

__global__ void __launch_bounds__(128, 2)
mma_gemm_single(const __half* __restrict__ A, const __half* __restrict__ B,
                const float* __restrict__ bias, float* __restrict__ C) {
    extern __shared__ char smc[];
    gemm_tile<false, false>(A, B, bias, C, DM, blockIdx.y * 128, blockIdx.x * 128, smc);
}

// ---------------- prep: LayerNorm rows + weight transpose ----------------
__global__ void prep_kernel(const float* __restrict__ x, const float* __restrict__ g,
                            const float* __restrict__ bta,
                            const float* __restrict__ wq, const float* __restrict__ wg,
                            const float* __restrict__ wp) {
    int tid = threadIdx.x;
    if (blockIdx.x < NTOK) {
        __shared__ float red0[8], red1[8];
        int row = blockIdx.x;
        const float* xrp = x + (size_t)row * DM;
        float4 xv = *(const float4*)(xrp + tid * 4);
        float s  = xv.x + xv.y + xv.z + xv.w;
        float s2 = xv.x*xv.x + xv.y*xv.y + xv.z*xv.z + xv.w*xv.w;
        #pragma unroll
        for (int o = 16; o > 0; o >>= 1) {
            s  += __shfl_xor_sync(0xffffffffu, s,  o);
            s2 += __shfl_xor_sync(0xffffffffu, s2, o);
        }
        int w = tid >> 5;
        if ((tid & 31) == 0) { red0[w] = s; red1[w] = s2; }
        __syncthreads();
        if (tid < 32) {
            s  = (tid < 8) ? red0[tid] : 0.f;
            s2 = (tid < 8) ? red1[tid] : 0.f;
            #pragma unroll
            for (int o = 4; o > 0; o >>= 1) {
                s  += __shfl_xor_sync(0xffffffffu, s,  o);
                s2 += __shfl_xor_sync(0xffffffffu, s2, o);
            }
            if (tid == 0) { red0[0] = s; red1[0] = s2; }
        }
        __syncthreads();
        float mu   = red0[0] * (1.f / DM);
        float var  = red1[0] * (1.f / DM) - mu * mu;
        float rstd = rsqrtf(var + 1e-5f);
        float4 gv = *(const float4*)(g + tid * 4);
        float4 bv = *(const float4*)(bta + tid * 4);
        __half2* xn2 = (__half2*)(g_xnorm_h + (size_t)row * DM) + tid * 2;
        __half2* xr2 = (__half2*)(g_xr_h    + (size_t)row * DM) + tid * 2;
        xn2[0] = __floats2half2_rn((xv.x - mu) * rstd * gv.x + bv.x,
                                   (xv.y - mu) * rstd * gv.y + bv.y);
        xn2[1] = __floats2half2_rn((xv.z - mu) * rstd * gv.z + bv.z,
                                   (xv.w - mu) * rstd * gv.w + bv.w);
        xr2[0] = __floats2half2_rn(xv.x, xv.y);
        xr2[1] = __floats2half2_rn(xv.z, xv.w);
    } else {
        __shared__ float t[32][33];
        int idx = blockIdx.x - NTOK;
        int bxg = idx % 160;
        int by  = (idx / 160) * 32;
        const float* W; __half* WT; int N, bx;
        if (bxg < 96)      { W = wq; WT = g_wqkv_h;  N = 3 * DM; bx = bxg * 32; }
        else if (bxg < 128){ W = wg; WT = g_wgate_h; N = DM;     bx = (bxg - 96) * 32; }
        else               { W = wp; WT = g_wproj_h; N = DM;     bx = (bxg - 128) * 32; }
        int xx = tid & 31, yy = tid >> 5;
        #pragma unroll
        for (int i = 0; i < 32; i += 8)
            t[yy + i][xx] = W[(size_t)(by + yy + i) * N + bx + xx];
        __syncthreads();
        #pragma unroll
        for (int i = 0; i < 32; i += 8)
            WT[(size_t)(bx + yy + i) * DM + by + xx] = __float2half(t[xx][yy + i]);
    }
}

// ---------------- fused gate-normalize + head split + elu+1 ----------------
__global__ void gatesplit_kernel() {
    __shared__ float red[8];
    int n = blockIdx.x, tid = threadIdx.x;
    const __half2* g2 = (const __half2*)(g_gate_h + (size_t)n * DM);
    float2 g0 = __half22float2(g2[tid * 2]);
    float2 g1 = __half22float2(g2[tid * 2 + 1]);
    float s = g0.x + g0.y + g1.x + g1.y;
    #pragma unroll
    for (int o = 16; o > 0; o >>= 1) s += __shfl_xor_sync(0xffffffffu, s, o);
    if ((tid & 31) == 0) red[tid >> 5] = s;
    __syncthreads();
    if (tid < 32) {
        s = (tid < 8) ? red[tid] : 0.f;
        #pragma unroll
        for (int o = 4; o > 0; o >>= 1) s += __shfl_xor_sync(0xffffffffu, s, o);
        if (tid == 0) red[0] = s;
    }
    __syncthreads();
    float scale = 1.f / (red[0] * (1.f / DM) + 1e-5f);

    int cix = tid * 4;
    int h = cix >> 6, e = cix & 63;
    int b = n >> 11, t = n & 2047;
    const __half2* qkv2 = (const __half2*)(g_qkv_h + (size_t)n * 3072);
    float2 q0 = __half22float2(qkv2[tid * 2]);
    float2 q1 = __half22float2(qkv2[tid * 2 + 1]);
    float2 k0 = __half22float2(qkv2[512 + tid * 2]);
    float2 k1 = __half22float2(qkv2[512 + tid * 2 + 1]);
    float2 v0 = __half22float2(qkv2[1024 + tid * 2]);
    float2 v1 = __half22float2(qkv2[1024 + tid * 2 + 1]);
    float gn0 = g0.x * scale, gn1 = g0.y * scale, gn2 = g1.x * scale, gn3 = g1.y * scale;
    q0.x *= gn0; q0.y *= gn1; q1.x *= gn2; q1.y *= gn3;
    k0.x *= gn0; k0.y *= gn1; k1.x *= gn2; k1.y *= gn3;
    q0.x = (q0.x > 0.f) ? q0.x + 1.f : expf(q0.x);
    q0.y = (q0.y > 0.f) ? q0.y + 1.f : expf(q0.y);
    q1.x = (q1.x > 0.f) ? q1.x + 1.f : expf(q1.x);
    q1.y = (q1.y > 0.f) ? q1.y + 1.f : expf(q1.y);
    k0.x = (k0.x > 0.f) ? k0.x + 1.f : expf(k0.x);
    k0.y = (k0.y > 0.f) ? k0.y + 1.f : expf(k0.y);
    k1.x = (k1.x > 0.f) ? k1.x + 1.f : expf(k1.x);
    k1.y = (k1.y > 0.f) ? k1.y + 1.f : expf(k1.y);
    size_t o = ((size_t)(b * NH + h) * SEQ + t) * DH + e;
    *(__half2*)(g_qh_h + o)     = __floats2half2_rn(q0.x, q0.y);
    *(__half2*)(g_qh_h + o + 2) = __floats2half2_rn(q1.x, q1.y);
    *(__half2*)(g_kh_h + o)     = __floats2half2_rn(k0.x, k0.y);
    *(__half2*)(g_kh_h + o + 2) = __floats2half2_rn(k1.x, k1.y);
    *(__half2*)(g_vh_h + o)     = __floats2half2_rn(v0.x, v0.y);
    *(__half2*)(g_vh_h + o + 2) = __floats2half2_rn(v1.x, v1.y);
}

// ---------------- pass A (tensor-core): KV[m][d] = v^T @ k, ksum ----------------
// smem: kt[64][136], vt[64][136] halves (transposed [d][t] and [m][t])
#define PA_KT 0
#define PA_VT (64*136)
#define PA_SMEM ((2*64*136)*2)    // 34816 B

__global__ void __launch_bounds__(128, 4) passA_kernel() {
    extern __shared__ __half pash[];
    __half* kt_sm = pash + PA_KT;
    __half* vt_sm = pash + PA_VT;
    uint32_t sbase = smem_u32(pash);

    int blk = blockIdx.x;
    int bh = blk / NCH, c = blk % NCH;
    int tid = threadIdx.x;
    int wid = tid >> 5, lane = tid & 31;
    int gid = lane >> 2, tig = lane & 3;
    int wm = wid * 16;

    const __half* kb = g_kh_h + ((size_t)bh * SEQ + c * CHUNK) * DH;
    const __half* vb = g_vh_h + ((size_t)bh * SEQ + c * CHUNK) * DH;

    // transpose k, v: [t=128][d=64] -> [d][t] rows padded 136
    #pragma unroll
    for (int l = 0; l < 32; l++) {
        int id = tid + l * 128;                 // 4096 half2 per matrix
        int s = id & 127, m2 = id >> 7;         // s = t, m2 = d-pair
        __half2 k2 = *(const __half2*)(kb + s * 64 + m2 * 2);
        __half2 v2 = *(const __half2*)(vb + s * 64 + m2 * 2);
        kt_sm[(m2 * 2    ) * 136 + s] = __low2half(k2);
        kt_sm[(m2 * 2 + 1) * 136 + s] = __high2half(k2);
        vt_sm[(m2 * 2    ) * 136 + s] = __low2half(v2);
        vt_sm[(m2 * 2 + 1) * 136 + s] = __high2half(v2);
    }
    __syncthreads();

    // ksum[d] = sum_t k[t][d] (threads 0..63, contiguous row)
    if (tid < 64) {
        float s = 0.f;
        const __half2* row = (const __half2*)(kt_sm + tid * 136);
        #pragma unroll 16
        for (int j = 0; j < 64; j++) {
            float2 f = __half22float2(row[j]);
            s += f.x + f.y;
        }
        g_ksum[blk * DH + tid] = s;
    }

    // KV[m][d]: A = vt [m][t], B = kt [d][t]; warp m-rows [wm, wm+16)
    float acc[8][4];
    #pragma unroll
    for (int nf = 0; nf < 8; nf++)
        #pragma unroll
        for (int r = 0; r < 4; r++) acc[nf][r] = 0.f;

    uint32_t aO = sbase + PA_VT * 2 + ((wm + (lane & 15)) * 136 + (lane >> 4) * 8) * 2;
    uint32_t bO = sbase + PA_KT * 2 + ((lane & 7) * 136 + ((lane >> 3) & 1) * 8) * 2;
    #pragma unroll
    for (int ks = 0; ks < 8; ks++) {
        uint32_t a[4], bfr[8][2];
        ldsm_x4(a, aO + (ks * 16) * 2);
        #pragma unroll
        for (int nf = 0; nf < 8; nf++)
            ldsm_x2(bfr[nf], bO + (nf * 8 * 136 + ks * 16) * 2);
        #pragma unroll
        for (int nf = 0; nf < 8; nf++)
            mma_f16(acc[nf], a, bfr[nf]);
    }

    float* kvo = g_kv + (size_t)blk * (DH * DH);
    #pragma unroll
    for (int nf = 0; nf < 8; nf++) {
        int d0 = nf * 8 + tig * 2;
        *(float2*)(kvo + (wm + gid) * 64 + d0)     = make_float2(acc[nf][0], acc[nf][1]);
        *(float2*)(kvo + (wm + gid + 8) * 64 + d0) = make_float2(acc[nf][2], acc[nf][3]);
    }
}

// ---------------- pass B: exclusive prefix over chunks ----------------
__global__ void passB_kernel() {
    int bh = blockIdx.y;
    int e = blockIdx.x * 256 + threadIdx.x;
    float run = 0.f;
    #pragma unroll
    for (int c = 0; c < NCH; c++) {
        size_t idx = ((size_t)bh * NCH + c) * (DH * DH) + e;
        g_kvpre[idx] = run;
        run += g_kv[idx];
    }
    if (blockIdx.x == 0 && threadIdx.x < DH) {
        float r2 = 0.f;
        #pragma unroll
        for (int c = 0; c < NCH; c++) {
            size_t idx = ((size_t)bh * NCH + c) * DH + threadIdx.x;
            g_kspre[idx] = r2;
            r2 += g_ksum[idx];
        }
    }
}

// ---------------- pass C: tensor-core flash-style ----------------
#define PC_Q   0
#define PC_K   (128*72)
#define PC_VT  (PC_K + 128*72)
#define PC_SP  (PC_VT + 64*136)
#define PC_SC  (PC_SP + 64*72)
#define PC_HALVES (PC_SC + 128*136)
#define PC_SMEM (PC_HALVES*2 + (64+128)*4)   // 99072 B

__global__ void __launch_bounds__(128, 2) passC_kernel() {
    extern __shared__ __half smh[];
    __half* q_sm  = smh + PC_Q;
    __half* k_sm  = smh + PC_K;
    __half* vt_sm = smh + PC_VT;
    __half* sp_sm = smh + PC_SP;
    __half* sc_sm = smh + PC_SC;
    float* kp_sm  = (float*)(smh + PC_HALVES);
    float* den_sm = kp_sm + 64;
    uint32_t sbase = smem_u32(smh);

    int blk = blockIdx.x;
    int bh = blk / NCH, c = blk % NCH;
    int b = bh / NH, h = bh % NH;
    int tid = threadIdx.x;
    int wid = tid >> 5, lane = tid & 31;
    int gid = lane >> 2, tig = lane & 3;
    int wm = wid * 32;

    const __half* qb = g_qh_h + ((size_t)bh * SEQ + c * CHUNK) * DH;
    const __half* kb = g_kh_h + ((size_t)bh * SEQ + c * CHUNK) * DH;
    const __half* vb = g_vh_h + ((size_t)bh * SEQ + c * CHUNK) * DH;

    #pragma unroll
    for (int l = 0; l < 8; l++) {
        int id = tid + l * 128;
        int r = id >> 3, c8 = (id & 7) * 8;
        *(uint4*)(q_sm + r * 72 + c8) = *(const uint4*)(qb + r * 64 + c8);
        *(uint4*)(k_sm + r * 72 + c8) = *(const uint4*)(kb + r * 64 + c8);
    }
    #pragma unroll
    for (int l = 0; l < 32; l++) {
        int id = tid + l * 128;
        int s = id & 127, m2 = id >> 7;
        __half2 v2 = *(const __half2*)(vb + s * 64 + m2 * 2);
        vt_sm[(m2 * 2    ) * 136 + s] = __low2half(v2);
        vt_sm[(m2 * 2 + 1) * 136 + s] = __high2half(v2);
    }
    const float* spg = g_kvpre + (size_t)blk * 4096;
    #pragma unroll
    for (int l = 0; l < 8; l++) {
        int id = tid + l * 128;
        int m = id >> 4, d4 = (id & 15) * 4;
        float4 s4 = *(const float4*)(spg + m * 64 + d4);
        __half2* dst = (__half2*)(sp_sm + m * 72 + d4);
        dst[0] = __floats2half2_rn(s4.x, s4.y);
        dst[1] = __floats2half2_rn(s4.z, s4.w);
    }
    if (tid < 64) kp_sm[tid] = g_kspre[(size_t)blk * 64 + tid];
    __syncthreads();

    {
        float c1[2][16][4];
        #pragma unroll
        for (int mf = 0; mf < 2; mf++)
            #pragma unroll
            for (int nf = 0; nf < 16; nf++)
                #pragma unroll
                for (int r = 0; r < 4; r++) c1[mf][nf][r] = 0.f;

        uint32_t aO = sbase + PC_Q * 2 + ((wm + (lane & 15)) * 72 + (lane >> 4) * 8) * 2;
        uint32_t bO = sbase + PC_K * 2 + ((lane & 7) * 72 + ((lane >> 3) & 1) * 8) * 2;
        #pragma unroll
        for (int ks = 0; ks < 4; ks++) {
            uint32_t a[2][4], bfr[16][2];
            #pragma unroll
            for (int mf = 0; mf < 2; mf++)
                ldsm_x4(a[mf], aO + (mf * 16 * 72 + ks * 16) * 2);
            #pragma unroll
            for (int nf = 0; nf < 16; nf++)
                ldsm_x2(bfr[nf], bO + (nf * 8 * 72 + ks * 16) * 2);
            #pragma unroll
            for (int mf = 0; mf < 2; mf++)
                #pragma unroll
                for (int nf = 0; nf < 16; nf++)
                    mma_f16(c1[mf][nf], a[mf], bfr[nf]);
        }
        #pragma unroll
        for (int mf = 0; mf < 2; mf++) {
            int t0 = wm + mf * 16 + gid;
            #pragma unroll
            for (int nf = 0; nf < 16; nf++) {
                int s0 = nf * 8 + tig * 2;
                float v0 = (s0     <= t0) ? c1[mf][nf][0] : 0.f;
                float v1 = (s0 + 1 <= t0) ? c1[mf][nf][1] : 0.f;
                float v2 = (s0     <= t0 + 8) ? c1[mf][nf][2] : 0.f;
                float v3 = (s0 + 1 <= t0 + 8) ? c1[mf][nf][3] : 0.f;
                *(__half2*)(sc_sm + t0 * 136 + s0)       = __floats2half2_rn(v0, v1);
                *(__half2*)(sc_sm + (t0 + 8) * 136 + s0) = __floats2half2_rn(v2, v3);
            }
        }
    }
    __syncthreads();

    {
        int t = tid;
        float s = 0.f;
        #pragma unroll 16
        for (int j = 0; j < 128; j += 2) {
            float2 f = __half22float2(*(__half2*)(sc_sm + t * 136 + j));
            s += f.x + f.y;
        }
        #pragma unroll 8
        for (int d = 0; d < 64; d += 2) {
            float2 qf = __half22float2(*(__half2*)(q_sm + t * 72 + d));
            s += qf.x * kp_sm[d] + qf.y * kp_sm[d + 1];
        }
        den_sm[t] = 1.f / (s + 1e-5f);
    }
    __syncthreads();

    float c2[2][8][4];
    #pragma unroll
    for (int mf = 0; mf < 2; mf++)
        #pragma unroll
        for (int nf = 0; nf < 8; nf++)
            #pragma unroll
            for (int r = 0; r < 4; r++) c2[mf][nf][r] = 0.f;

    {
        uint32_t aO = sbase + PC_SC * 2 + ((wm + (lane & 15)) * 136 + (lane >> 4) * 8) * 2;
        uint32_t bO = sbase + PC_VT * 2 + ((lane & 7) * 136 + ((lane >> 3) & 1) * 8) * 2;
        #pragma unroll
        for (int ks = 0; ks < 8; ks++) {
            uint32_t a[2][4], bfr[8][2];
            #pragma unroll
            for (int mf = 0; mf < 2; mf++)
                ldsm_x4(a[mf], aO + (mf * 16 * 136 + ks * 16) * 2);
            #pragma unroll
            for (int nf = 0; nf < 8; nf++)
                ldsm_x2(bfr[nf], bO + (nf * 8 * 136 + ks * 16) * 2);
            #pragma unroll
            for (int mf = 0; mf < 2; mf++)
                #pragma unroll
                for (int nf = 0; nf < 8; nf++)
                    mma_f16(c2[mf][nf], a[mf], bfr[nf]);
        }
    }
    {
        uint32_t aO = sbase + PC_Q * 2 + ((wm + (lane & 15)) * 72 + (lane >> 4) * 8) * 2;
        uint32_t bO = sbase + PC_SP * 2 + ((lane & 7) * 72 + ((lane >> 3) & 1) * 8) * 2;
        #pragma unroll
        for (int ks = 0; ks < 4; ks++) {
            uint32_t a[2][4], bfr[8][2];
            #pragma unroll
            for (int mf = 0; mf < 2; mf++)
                ldsm_x4(a[mf], aO + (mf * 16 * 72 + ks * 16) * 2);
            #pragma unroll
            for (int nf = 0; nf < 8; nf++)
                ldsm_x2(bfr[nf], bO + (nf * 8 * 72 + ks * 16) * 2);
            #pragma unroll
            for (int mf = 0; mf < 2; mf++)
                #pragma unroll
                for (int nf = 0; nf < 8; nf++)
                    mma_f16(c2[mf][nf], a[mf], bfr[nf]);
        }
    }

    #pragma unroll
    for (int mf = 0; mf < 2; mf++) {
        int t0 = wm + mf * 16 + gid;
        int tok0 = b * SEQ + c * CHUNK + t0;
        float i0 = den_sm[t0], i1 = den_sm[t0 + 8];
        #pragma unroll
        for (int nf = 0; nf < 8; nf++) {
            int m0 = nf * 8 + tig * 2;
            *(__half2*)(g_ctx_h + (size_t)tok0 * DM + h * DH + m0) =
                __floats2half2_rn(c2[mf][nf][0] * i0, c2[mf][nf][1] * i0);
            *(__half2*)(g_ctx_h + (size_t)(tok0 + 8) * DM + h * DH + m0) =
                __floats2half2_rn(c2[mf][nf][2] * i1, c2[mf][nf][3] * i1);
        }
    }
}

// ---------------- launch ----------------
extern "C" void kernel_launch(void* const* d_in, const int* in_sizes, int n_in,
                              void* d_out, int out_size) {
    const float* x      = (const float*)d_in[0];
    const float* ln_g   = (const float*)d_in[1];
    const float* ln_b   = (const float*)d_in[2];
    const float* w_qkv  = (const float*)d_in[3];
    const float* b_qkv  = (const float*)d_in[4];
    const float* w_gate = (const float*)d_in[5];
    const float* b_gate = (const float*)d_in[6];
    const float* w_proj = (const float*)d_in[7];
    const float* b_proj = (const float*)d_in[8];
    float* out = (float*)d_out;

    void *p_xnorm, *p_xr, *p_ctx, *p_wqkv, *p_wgate, *p_wproj;
    cudaGetSymbolAddress(&p_xnorm, g_xnorm_h);
    cudaGetSymbolAddress(&p_xr,    g_xr_h);
    cudaGetSymbolAddress(&p_ctx,   g_ctx_h);
    cudaGetSymbolAddress(&p_wqkv,  g_wqkv_h);
    cudaGetSymbolAddress(&p_wgate, g_wgate_h);
    cudaGetSymbolAddress(&p_wproj, g_wproj_h);

    cudaFuncSetAttribute(passC_kernel, cudaFuncAttributeMaxDynamicSharedMemorySize, PC_SMEM);
    cudaFuncSetAttribute(passA_kernel, cudaFuncAttributeMaxDynamicSharedMemorySize, PA_SMEM);
    cudaFuncSetAttribute(mma_gemm_dual,   cudaFuncAttributeMaxDynamicSharedMemorySize, GEMM_SMEM_BYTES);
    cudaFuncSetAttribute(mma_gemm_single, cudaFuncAttributeMaxDynamicSharedMemorySize, GEMM_SMEM_BYTES);

    // 0+1. prep: LayerNorm + weight transpose
    prep_kernel<<<NTOK + 160 * 32, 256>>>(x, ln_g, ln_b, w_qkv, w_gate, w_proj);
    // 2+3. persistent dual GEMM (BK=64)
    mma_gemm_dual<<<296, 128, GEMM_SMEM_BYTES>>>(
        (const __half*)p_xnorm, (const __half*)p_wqkv, b_qkv,
        (const __half*)p_xr,    (const __half*)p_wgate, b_gate);
    // 4+5. fused gate-normalize + split + elu+1
    gatesplit_kernel<<<NTOK, 256>>>();
    // 6-8. chunked causal linear attention (tensor-core passA + passC)
    passA_kernel<<<NBH * NCH, 128, PA_SMEM>>>();
    passB_kernel<<<dim3(16, NBH), 256>>>();
    passC_kernel<<<NBH * NCH, 128, PC_SMEM>>>();
    // 9. projection (BK=64)
    mma_gemm_single<<<dim3(DM / 128, NTOK / 128), 128, GEMM_SMEM_BYTES>>>(
        (const __half*)p_ctx, (const __half*)p_wproj, b_proj, out);
}

// round 17
// speedup vs baseline: 1.1283x; 1.1283x over previous
#include <cuda_runtime.h>
#include <cuda_fp16.h>
#include <math.h>
#include <stdint.h>

// ---------------- problem constants ----------------
#define BATCH 2
#define SEQ   2048
#define DM    1024
#define NH    16
#define DH    64
#define NTOK  (BATCH*SEQ)        // 4096
#define CHUNK 128
#define NCH   (SEQ/CHUNK)        // 16
#define NBH   (BATCH*NH)         // 32

// ---------------- scratch (device globals; no allocs allowed) ----------------
__device__ __half  g_xnorm_h[NTOK*DM];
__device__ __half  g_xr_h   [NTOK*DM];
__device__ __half  g_qkv_h  [NTOK*3*DM];
__device__ __half  g_gate_h [NTOK*DM];
__device__ __half  g_qh_h   [NBH*SEQ*DH];
__device__ __half  g_kh_h   [NBH*SEQ*DH];
__device__ __half  g_vh_h   [NBH*SEQ*DH];
__device__ float   g_kv     [NBH*NCH*DH*DH];   // per chunk: [m][d]
__device__ float   g_kvpre  [NBH*NCH*DH*DH];   // [m][d]
__device__ float   g_ksum   [NBH*NCH*DH];
__device__ float   g_kspre  [NBH*NCH*DH];
__device__ __half  g_ctx_h  [NTOK*DM];
__device__ __half  g_wqkv_h [(3*DM)*DM];   // [n][k] fp16 (transposed)
__device__ __half  g_wgate_h[DM*DM];       // [n][k]
__device__ __half  g_wproj_h[DM*DM];       // [n][k]

// ---------------- helpers ----------------
__device__ __forceinline__ void mma_f16(float* c, const uint32_t* a, const uint32_t* b) {
    asm volatile(
        "mma.sync.aligned.m16n8k16.row.col.f32.f16.f16.f32 "
        "{%0,%1,%2,%3}, {%4,%5,%6,%7}, {%8,%9}, {%0,%1,%2,%3};"
        : "+f"(c[0]), "+f"(c[1]), "+f"(c[2]), "+f"(c[3])
        : "r"(a[0]), "r"(a[1]), "r"(a[2]), "r"(a[3]), "r"(b[0]), "r"(b[1]));
}
__device__ __forceinline__ void ldsm_x4(uint32_t* r, uint32_t addr) {
    asm volatile("ldmatrix.sync.aligned.m8n8.x4.shared.b16 {%0,%1,%2,%3}, [%4];"
        : "=r"(r[0]), "=r"(r[1]), "=r"(r[2]), "=r"(r[3]) : "r"(addr));
}
__device__ __forceinline__ void ldsm_x2(uint32_t* r, uint32_t addr) {
    asm volatile("ldmatrix.sync.aligned.m8n8.x2.shared.b16 {%0,%1}, [%2];"
        : "=r"(r[0]), "=r"(r[1]) : "r"(addr));
}
__device__ __forceinline__ void ldsm_x4_t(uint32_t* r, uint32_t addr) {
    asm volatile("ldmatrix.sync.aligned.m8n8.x4.trans.shared.b16 {%0,%1,%2,%3}, [%4];"
        : "=r"(r[0]), "=r"(r[1]), "=r"(r[2]), "=r"(r[3]) : "r"(addr));
}
__device__ __forceinline__ void ldsm_x2_t(uint32_t* r, uint32_t addr) {
    asm volatile("ldmatrix.sync.aligned.m8n8.x2.trans.shared.b16 {%0,%1}, [%2];"
        : "=r"(r[0]), "=r"(r[1]) : "r"(addr));
}
__device__ __forceinline__ uint32_t smem_u32(const void* p) {
    uint32_t a;
    asm("{ .reg .u64 t; cvta.to.shared.u64 t, %1; cvt.u32.u64 %0, t; }" : "=r"(a) : "l"(p));
    return a;
}
__device__ __forceinline__ void cp16(uint32_t dst, const void* src) {
    asm volatile("cp.async.cg.shared.global [%0], [%1], 16;" :: "r"(dst), "l"(src));
}
#define CP_COMMIT() asm volatile("cp.async.commit_group;" ::: "memory")
#define CP_WAIT(n)  asm volatile("cp.async.wait_group %0;" :: "n"(n) : "memory")

// ================= fp16 mma.sync GEMM core: BK=64 =================
#define ROW_H 72
#define ASTB (128*ROW_H*2)
#define BSTB (128*ROW_H*2)
#define GEMM_SMEM_BYTES (3*(ASTB+BSTB))  // 110592
#define NKT (DM/64)

template<bool SIGMOID, bool HALF_OUT>
__device__ __forceinline__ void gemm_tile(
    const __half* __restrict__ A, const __half* __restrict__ B,
    const float* __restrict__ bias, void* __restrict__ Cv,
    int N, int bm0, int bn0, char* sm) {

    uint32_t sA = smem_u32(sm);
    uint32_t sB = sA + 3 * ASTB;
    int tid = threadIdx.x;
    int wid = tid >> 5, lane = tid & 31;
    int gid = lane >> 2, tig = lane & 3;
    int wm = (wid & 1) * 64, wn = (wid >> 1) * 64;

    float c[4][8][4];
    #pragma unroll
    for (int mf = 0; mf < 4; mf++)
        #pragma unroll
        for (int nf = 0; nf < 8; nf++)
            #pragma unroll
            for (int r = 0; r < 4; r++) c[mf][nf][r] = 0.f;

    auto stage = [&](int s, int kt) {
        const __half* Ab = A + (size_t)bm0 * DM + kt * 64;
        const __half* Bb = B + (size_t)bn0 * DM + kt * 64;
        uint32_t sAb = sA + s * ASTB;
        uint32_t sBb = sB + s * BSTB;
        #pragma unroll
        for (int l = 0; l < 8; l++) {
            int id = tid + l * 128;
            int r  = id >> 3, ch = id & 7;
            cp16(sAb + r * (ROW_H * 2) + ch * 16, Ab + (size_t)r * DM + ch * 8);
            cp16(sBb + r * (ROW_H * 2) + ch * 16, Bb + (size_t)r * DM + ch * 8);
        }
    };

    uint32_t aOff = (uint32_t)(((wm + (lane & 15)) * ROW_H + (lane >> 4) * 8) * 2);
    uint32_t bOff = (uint32_t)(((wn + (lane & 7)) * ROW_H + ((lane >> 3) & 1) * 8) * 2);

    stage(0, 0); CP_COMMIT();
    stage(1, 1); CP_COMMIT();

    for (int kt = 0; kt < NKT; kt++) {
        if (kt + 1 < NKT) { CP_WAIT(1); } else { CP_WAIT(0); }
        __syncthreads();

        int buf = kt % 3;
        uint32_t aBase = sA + buf * ASTB + aOff;
        uint32_t bBase = sB + buf * BSTB + bOff;
        #pragma unroll
        for (int ks = 0; ks < 4; ks++) {
            uint32_t a[4][4], b[8][2];
            #pragma unroll
            for (int mf = 0; mf < 4; mf++)
                ldsm_x4(a[mf], aBase + (mf * 16 * ROW_H + ks * 16) * 2);
            #pragma unroll
            for (int nf = 0; nf < 8; nf++)
                ldsm_x2(b[nf], bBase + (nf * 8 * ROW_H + ks * 16) * 2);
            #pragma unroll
            for (int mf = 0; mf < 4; mf++)
                #pragma unroll
                for (int nf = 0; nf < 8; nf++)
                    mma_f16(c[mf][nf], a[mf], b[nf]);
        }

        if (kt + 2 < NKT) { stage((kt + 2) % 3, kt + 2); CP_COMMIT(); }
    }

    #pragma unroll
    for (int mf = 0; mf < 4; mf++) {
        int row = bm0 + wm + mf * 16 + gid;
        #pragma unroll
        for (int nf = 0; nf < 8; nf++) {
            int col = bn0 + wn + nf * 8 + tig * 2;
            float b0 = bias[col], b1 = bias[col + 1];
            float2 o0 = make_float2(c[mf][nf][0] + b0, c[mf][nf][1] + b1);
            float2 o1 = make_float2(c[mf][nf][2] + b0, c[mf][nf][3] + b1);
            if (SIGMOID) {
                o0.x = 1.f / (1.f + expf(-o0.x)); o0.y = 1.f / (1.f + expf(-o0.y));
                o1.x = 1.f / (1.f + expf(-o1.x)); o1.y = 1.f / (1.f + expf(-o1.y));
            }
            if (HALF_OUT) {
                __half* C = (__half*)Cv;
                *(__half2*)(C + (size_t)row * N + col)       = __floats2half2_rn(o0.x, o0.y);
                *(__half2*)(C + (size_t)(row + 8) * N + col) = __floats2half2_rn(o1.x, o1.y);
            } else {
                float* C = (float*)Cv;
                *(float2*)(C + (size_t)row * N + col) = o0;
                *(float2*)(C + (size_t)(row + 8) * N + col) = o1;
            }
        }
    }
}

#define QKV_TILES 768
#define ALL_TILES (QKV_TILES + 256)

__global__ void __launch_bounds__(128, 2)
mma_gemm_dual(const __half* __restrict__ Aq, const __half* __restrict__ Bq,
              const float* __restrict__ biasq,
              const __half* __restrict__ Ag, const __half* __restrict__ Bg,
              const float* __restrict__ biasg) {
    extern __shared__ char smc[];
    for (int it = blockIdx.x; it < ALL_TILES; it += gridDim.x) {
        __syncthreads();
        if (it < QKV_TILES) {
            int bm = it / 24, bn = it % 24;
            gemm_tile<false, true>(Aq, Bq, biasq, g_qkv_h, 3 * DM, bm * 128, bn * 128, smc);
        } else {
            int t2 = it - QKV_TILES;
            int bm = t2 / 8, bn = t2 % 8;
            gemm_tile<true, true>(Ag, Bg, biasg, g_gate_h, DM, bm * 128, bn * 128, smc);
        }
    }
}

__global__ void __launch_bounds__(128, 2)
mma_gemm_single(const __half* __restrict__ A, const __half* __restrict__ B,
                const float* __restrict__ bias, float* __restrict__ C) {
    extern __shared__ char smc[];
    gemm_tile<false, false>(A, B, bias, C, DM, blockIdx.y * 128, blockIdx.x * 128, smc);
}

// ---------------- prep: LayerNorm rows + weight transpose ----------------
__global__ void prep_kernel(const float* __restrict__ x, const float* __restrict__ g,
                            const float* __restrict__ bta,
                            const float* __restrict__ wq, const float* __restrict__ wg,
                            const float* __restrict__ wp) {
    int tid = threadIdx.x;
    if (blockIdx.x < NTOK) {
        __shared__ float red0[8], red1[8];
        int row = blockIdx.x;
        const float* xrp = x + (size_t)row * DM;
        float4 xv = *(const float4*)(xrp + tid * 4);
        float s  = xv.x + xv.y + xv.z + xv.w;
        float s2 = xv.x*xv.x + xv.y*xv.y + xv.z*xv.z + xv.w*xv.w;
        #pragma unroll
        for (int o = 16; o > 0; o >>= 1) {
            s  += __shfl_xor_sync(0xffffffffu, s,  o);
            s2 += __shfl_xor_sync(0xffffffffu, s2, o);
        }
        int w = tid >> 5;
        if ((tid & 31) == 0) { red0[w] = s; red1[w] = s2; }
        __syncthreads();
        if (tid < 32) {
            s  = (tid < 8) ? red0[tid] : 0.f;
            s2 = (tid < 8) ? red1[tid] : 0.f;
            #pragma unroll
            for (int o = 4; o > 0; o >>= 1) {
                s  += __shfl_xor_sync(0xffffffffu, s,  o);
                s2 += __shfl_xor_sync(0xffffffffu, s2, o);
            }
            if (tid == 0) { red0[0] = s; red1[0] = s2; }
        }
        __syncthreads();
        float mu   = red0[0] * (1.f / DM);
        float var  = red1[0] * (1.f / DM) - mu * mu;
        float rstd = rsqrtf(var + 1e-5f);
        float4 gv = *(const float4*)(g + tid * 4);
        float4 bv = *(const float4*)(bta + tid * 4);
        __half2* xn2 = (__half2*)(g_xnorm_h + (size_t)row * DM) + tid * 2;
        __half2* xr2 = (__half2*)(g_xr_h    + (size_t)row * DM) + tid * 2;
        xn2[0] = __floats2half2_rn((xv.x - mu) * rstd * gv.x + bv.x,
                                   (xv.y - mu) * rstd * gv.y + bv.y);
        xn2[1] = __floats2half2_rn((xv.z - mu) * rstd * gv.z + bv.z,
                                   (xv.w - mu) * rstd * gv.w + bv.w);
        xr2[0] = __floats2half2_rn(xv.x, xv.y);
        xr2[1] = __floats2half2_rn(xv.z, xv.w);
    } else {
        __shared__ float t[32][33];
        int idx = blockIdx.x - NTOK;
        int bxg = idx % 160;
        int by  = (idx / 160) * 32;
        const float* W; __half* WT; int N, bx;
        if (bxg < 96)      { W = wq; WT = g_wqkv_h;  N = 3 * DM; bx = bxg * 32; }
        else if (bxg < 128){ W = wg; WT = g_wgate_h; N = DM;     bx = (bxg - 96) * 32; }
        else               { W = wp; WT = g_wproj_h; N = DM;     bx = (bxg - 128) * 32; }
        int xx = tid & 31, yy = tid >> 5;
        #pragma unroll
        for (int i = 0; i < 32; i += 8)
            t[yy + i][xx] = W[(size_t)(by + yy + i) * N + bx + xx];
        __syncthreads();
        #pragma unroll
        for (int i = 0; i < 32; i += 8)
            WT[(size_t)(bx + yy + i) * DM + by + xx] = __float2half(t[xx][yy + i]);
    }
}

// ---------------- fused gate-normalize + head split + elu+1 ----------------
__global__ void gatesplit_kernel() {
    __shared__ float red[8];
    int n = blockIdx.x, tid = threadIdx.x;
    const __half2* g2 = (const __half2*)(g_gate_h + (size_t)n * DM);
    float2 g0 = __half22float2(g2[tid * 2]);
    float2 g1 = __half22float2(g2[tid * 2 + 1]);
    float s = g0.x + g0.y + g1.x + g1.y;
    #pragma unroll
    for (int o = 16; o > 0; o >>= 1) s += __shfl_xor_sync(0xffffffffu, s, o);
    if ((tid & 31) == 0) red[tid >> 5] = s;
    __syncthreads();
    if (tid < 32) {
        s = (tid < 8) ? red[tid] : 0.f;
        #pragma unroll
        for (int o = 4; o > 0; o >>= 1) s += __shfl_xor_sync(0xffffffffu, s, o);
        if (tid == 0) red[0] = s;
    }
    __syncthreads();
    float scale = 1.f / (red[0] * (1.f / DM) + 1e-5f);

    int cix = tid * 4;
    int h = cix >> 6, e = cix & 63;
    int b = n >> 11, t = n & 2047;
    const __half2* qkv2 = (const __half2*)(g_qkv_h + (size_t)n * 3072);
    float2 q0 = __half22float2(qkv2[tid * 2]);
    float2 q1 = __half22float2(qkv2[tid * 2 + 1]);
    float2 k0 = __half22float2(qkv2[512 + tid * 2]);
    float2 k1 = __half22float2(qkv2[512 + tid * 2 + 1]);
    float2 v0 = __half22float2(qkv2[1024 + tid * 2]);
    float2 v1 = __half22float2(qkv2[1024 + tid * 2 + 1]);
    float gn0 = g0.x * scale, gn1 = g0.y * scale, gn2 = g1.x * scale, gn3 = g1.y * scale;
    q0.x *= gn0; q0.y *= gn1; q1.x *= gn2; q1.y *= gn3;
    k0.x *= gn0; k0.y *= gn1; k1.x *= gn2; k1.y *= gn3;
    q0.x = (q0.x > 0.f) ? q0.x + 1.f : expf(q0.x);
    q0.y = (q0.y > 0.f) ? q0.y + 1.f : expf(q0.y);
    q1.x = (q1.x > 0.f) ? q1.x + 1.f : expf(q1.x);
    q1.y = (q1.y > 0.f) ? q1.y + 1.f : expf(q1.y);
    k0.x = (k0.x > 0.f) ? k0.x + 1.f : expf(k0.x);
    k0.y = (k0.y > 0.f) ? k0.y + 1.f : expf(k0.y);
    k1.x = (k1.x > 0.f) ? k1.x + 1.f : expf(k1.x);
    k1.y = (k1.y > 0.f) ? k1.y + 1.f : expf(k1.y);
    size_t o = ((size_t)(b * NH + h) * SEQ + t) * DH + e;
    *(__half2*)(g_qh_h + o)     = __floats2half2_rn(q0.x, q0.y);
    *(__half2*)(g_qh_h + o + 2) = __floats2half2_rn(q1.x, q1.y);
    *(__half2*)(g_kh_h + o)     = __floats2half2_rn(k0.x, k0.y);
    *(__half2*)(g_kh_h + o + 2) = __floats2half2_rn(k1.x, k1.y);
    *(__half2*)(g_vh_h + o)     = __floats2half2_rn(v0.x, v0.y);
    *(__half2*)(g_vh_h + o + 2) = __floats2half2_rn(v1.x, v1.y);
}

// ---------------- pass A (tensor-core, trans-ldmatrix): KV[m][d] = v^T @ k ----------------
// smem: k_sm[128][72], v_sm[128][72] natural layout
#define PA_K 0
#define PA_V (128*72)
#define PA_SMEM (2*128*72*2)    // 36864 B

__global__ void __launch_bounds__(128, 4) passA_kernel() {
    extern __shared__ __half pash[];
    __half* k_sm = pash + PA_K;
    __half* v_sm = pash + PA_V;
    uint32_t sbase = smem_u32(pash);

    int blk = blockIdx.x;
    int bh = blk / NCH, c = blk % NCH;
    int tid = threadIdx.x;
    int wid = tid >> 5, lane = tid & 31;
    int gid = lane >> 2, tig = lane & 3;
    int wm = wid * 16;

    const __half* kb = g_kh_h + ((size_t)bh * SEQ + c * CHUNK) * DH;
    const __half* vb = g_vh_h + ((size_t)bh * SEQ + c * CHUNK) * DH;

    // coalesced natural staging: [t][64] rows padded to 72
    #pragma unroll
    for (int l = 0; l < 8; l++) {
        int id = tid + l * 128;
        int r = id >> 3, c8 = (id & 7) * 8;
        *(uint4*)(k_sm + r * 72 + c8) = *(const uint4*)(kb + r * 64 + c8);
        *(uint4*)(v_sm + r * 72 + c8) = *(const uint4*)(vb + r * 64 + c8);
    }
    __syncthreads();

    // ksum[d] = sum_t k[t][d] (threads 0..63; consecutive d per instruction -> no conflicts)
    if (tid < 64) {
        float s = 0.f;
        #pragma unroll 8
        for (int t = 0; t < 128; t++) s += __half2float(k_sm[t * 72 + tid]);
        g_ksum[blk * DH + tid] = s;
    }

    // KV[m][d] via trans fragments from natural layout
    float acc[8][4];
    #pragma unroll
    for (int nf = 0; nf < 8; nf++)
        #pragma unroll
        for (int r = 0; r < 4; r++) acc[nf][r] = 0.f;

    int tpartA = (lane & 7) + ((lane >> 4) & 1) * 8;
    int mcolA  = wm + ((lane >> 3) & 1) * 8;
    uint32_t aO = sbase + PA_V * 2 + (tpartA * 72 + mcolA) * 2;
    int tpartB = (lane & 7) + ((lane >> 3) & 1) * 8;
    uint32_t bO = sbase + PA_K * 2 + (tpartB * 72) * 2;
    #pragma unroll
    for (int ks = 0; ks < 8; ks++) {
        uint32_t a[4], bfr[8][2];
        ldsm_x4_t(a, aO + (ks * 16 * 72) * 2);
        #pragma unroll
        for (int nf = 0; nf < 8; nf++)
            ldsm_x2_t(bfr[nf], bO + (ks * 16 * 72 + nf * 8) * 2);
        #pragma unroll
        for (int nf = 0; nf < 8; nf++)
            mma_f16(acc[nf], a, bfr[nf]);
    }

    float* kvo = g_kv + (size_t)blk * (DH * DH);
    #pragma unroll
    for (int nf = 0; nf < 8; nf++) {
        int d0 = nf * 8 + tig * 2;
        *(float2*)(kvo + (wm + gid) * 64 + d0)     = make_float2(acc[nf][0], acc[nf][1]);
        *(float2*)(kvo + (wm + gid + 8) * 64 + d0) = make_float2(acc[nf][2], acc[nf][3]);
    }
}

// ---------------- pass B: exclusive prefix over chunks ----------------
__global__ void passB_kernel() {
    int bh = blockIdx.y;
    int e = blockIdx.x * 256 + threadIdx.x;
    float run = 0.f;
    #pragma unroll
    for (int c = 0; c < NCH; c++) {
        size_t idx = ((size_t)bh * NCH + c) * (DH * DH) + e;
        g_kvpre[idx] = run;
        run += g_kv[idx];
    }
    if (blockIdx.x == 0 && threadIdx.x < DH) {
        float r2 = 0.f;
        #pragma unroll
        for (int c = 0; c < NCH; c++) {
            size_t idx = ((size_t)bh * NCH + c) * DH + threadIdx.x;
            g_kspre[idx] = r2;
            r2 += g_ksum[idx];
        }
    }
}

// ---------------- pass C: tensor-core flash-style (trans-ldmatrix for v) ----------------
#define PC_Q   0
#define PC_K   (128*72)
#define PC_V   (2*128*72)
#define PC_SP  (3*128*72)
#define PC_SC  (PC_SP + 64*72)
#define PC_HALVES (PC_SC + 128*136)
#define PC_SMEM (PC_HALVES*2 + (64+128)*4)   // 100096 B

__global__ void __launch_bounds__(128, 2) passC_kernel() {
    extern __shared__ __half smh[];
    __half* q_sm  = smh + PC_Q;
    __half* k_sm  = smh + PC_K;
    __half* v_sm  = smh + PC_V;
    __half* sp_sm = smh + PC_SP;
    __half* sc_sm = smh + PC_SC;
    float* kp_sm  = (float*)(smh + PC_HALVES);
    float* den_sm = kp_sm + 64;
    uint32_t sbase = smem_u32(smh);

    int blk = blockIdx.x;
    int bh = blk / NCH, c = blk % NCH;
    int b = bh / NH, h = bh % NH;
    int tid = threadIdx.x;
    int wid = tid >> 5, lane = tid & 31;
    int gid = lane >> 2, tig = lane & 3;
    int wm = wid * 32;

    const __half* qb = g_qh_h + ((size_t)bh * SEQ + c * CHUNK) * DH;
    const __half* kb = g_kh_h + ((size_t)bh * SEQ + c * CHUNK) * DH;
    const __half* vb = g_vh_h + ((size_t)bh * SEQ + c * CHUNK) * DH;

    #pragma unroll
    for (int l = 0; l < 8; l++) {
        int id = tid + l * 128;
        int r = id >> 3, c8 = (id & 7) * 8;
        *(uint4*)(q_sm + r * 72 + c8) = *(const uint4*)(qb + r * 64 + c8);
        *(uint4*)(k_sm + r * 72 + c8) = *(const uint4*)(kb + r * 64 + c8);
        *(uint4*)(v_sm + r * 72 + c8) = *(const uint4*)(vb + r * 64 + c8);
    }
    const float* spg = g_kvpre + (size_t)blk * 4096;
    #pragma unroll
    for (int l = 0; l < 8; l++) {
        int id = tid + l * 128;
        int m = id >> 4, d4 = (id & 15) * 4;
        float4 s4 = *(const float4*)(spg + m * 64 + d4);
        __half2* dst = (__half2*)(sp_sm + m * 72 + d4);
        dst[0] = __floats2half2_rn(s4.x, s4.y);
        dst[1] = __floats2half2_rn(s4.z, s4.w);
    }
    if (tid < 64) kp_sm[tid] = g_kspre[(size_t)blk * 64 + tid];
    __syncthreads();

    // Stage 1: scores = q @ k^T
    {
        float c1[2][16][4];
        #pragma unroll
        for (int mf = 0; mf < 2; mf++)
            #pragma unroll
            for (int nf = 0; nf < 16; nf++)
                #pragma unroll
                for (int r = 0; r < 4; r++) c1[mf][nf][r] = 0.f;

        uint32_t aO = sbase + PC_Q * 2 + ((wm + (lane & 15)) * 72 + (lane >> 4) * 8) * 2;
        uint32_t bO = sbase + PC_K * 2 + ((lane & 7) * 72 + ((lane >> 3) & 1) * 8) * 2;
        #pragma unroll
        for (int ks = 0; ks < 4; ks++) {
            uint32_t a[2][4], bfr[16][2];
            #pragma unroll
            for (int mf = 0; mf < 2; mf++)
                ldsm_x4(a[mf], aO + (mf * 16 * 72 + ks * 16) * 2);
            #pragma unroll
            for (int nf = 0; nf < 16; nf++)
                ldsm_x2(bfr[nf], bO + (nf * 8 * 72 + ks * 16) * 2);
            #pragma unroll
            for (int mf = 0; mf < 2; mf++)
                #pragma unroll
                for (int nf = 0; nf < 16; nf++)
                    mma_f16(c1[mf][nf], a[mf], bfr[nf]);
        }
        #pragma unroll
        for (int mf = 0; mf < 2; mf++) {
            int t0 = wm + mf * 16 + gid;
            #pragma unroll
            for (int nf = 0; nf < 16; nf++) {
                int s0 = nf * 8 + tig * 2;
                float v0 = (s0     <= t0) ? c1[mf][nf][0] : 0.f;
                float v1 = (s0 + 1 <= t0) ? c1[mf][nf][1] : 0.f;
                float v2 = (s0     <= t0 + 8) ? c1[mf][nf][2] : 0.f;
                float v3 = (s0 + 1 <= t0 + 8) ? c1[mf][nf][3] : 0.f;
                *(__half2*)(sc_sm + t0 * 136 + s0)       = __floats2half2_rn(v0, v1);
                *(__half2*)(sc_sm + (t0 + 8) * 136 + s0) = __floats2half2_rn(v2, v3);
            }
        }
    }
    __syncthreads();

    // den[t]
    {
        int t = tid;
        float s = 0.f;
        #pragma unroll 16
        for (int j = 0; j < 128; j += 2) {
            float2 f = __half22float2(*(__half2*)(sc_sm + t * 136 + j));
            s += f.x + f.y;
        }
        #pragma unroll 8
        for (int d = 0; d < 64; d += 2) {
            float2 qf = __half22float2(*(__half2*)(q_sm + t * 72 + d));
            s += qf.x * kp_sm[d] + qf.y * kp_sm[d + 1];
        }
        den_sm[t] = 1.f / (s + 1e-5f);
    }
    __syncthreads();

    // Stage 2: out = scores @ v (trans) + q @ S_pre^T
    float c2[2][8][4];
    #pragma unroll
    for (int mf = 0; mf < 2; mf++)
        #pragma unroll
        for (int nf = 0; nf < 8; nf++)
            #pragma unroll
            for (int r = 0; r < 4; r++) c2[mf][nf][r] = 0.f;

    {
        uint32_t aO = sbase + PC_SC * 2 + ((wm + (lane & 15)) * 136 + (lane >> 4) * 8) * 2;
        int tpartB = (lane & 7) + ((lane >> 3) & 1) * 8;
        uint32_t bO = sbase + PC_V * 2 + (tpartB * 72) * 2;
        #pragma unroll
        for (int ks = 0; ks < 8; ks++) {
            uint32_t a[2][4], bfr[8][2];
            #pragma unroll
            for (int mf = 0; mf < 2; mf++)
                ldsm_x4(a[mf], aO + (mf * 16 * 136 + ks * 16) * 2);
            #pragma unroll
            for (int nf = 0; nf < 8; nf++)
                ldsm_x2_t(bfr[nf], bO + (ks * 16 * 72 + nf * 8) * 2);
            #pragma unroll
            for (int mf = 0; mf < 2; mf++)
                #pragma unroll
                for (int nf = 0; nf < 8; nf++)
                    mma_f16(c2[mf][nf], a[mf], bfr[nf]);
        }
    }
    {
        uint32_t aO = sbase + PC_Q * 2 + ((wm + (lane & 15)) * 72 + (lane >> 4) * 8) * 2;
        uint32_t bO = sbase + PC_SP * 2 + ((lane & 7) * 72 + ((lane >> 3) & 1) * 8) * 2;
        #pragma unroll
        for (int ks = 0; ks < 4; ks++) {
            uint32_t a[2][4], bfr[8][2];
            #pragma unroll
            for (int mf = 0; mf < 2; mf++)
                ldsm_x4(a[mf], aO + (mf * 16 * 72 + ks * 16) * 2);
            #pragma unroll
            for (int nf = 0; nf < 8; nf++)
                ldsm_x2(bfr[nf], bO + (nf * 8 * 72 + ks * 16) * 2);
            #pragma unroll
            for (int mf = 0; mf < 2; mf++)
                #pragma unroll
                for (int nf = 0; nf < 8; nf++)
                    mma_f16(c2[mf][nf], a[mf], bfr[nf]);
        }
    }

    #pragma unroll
    for (int mf = 0; mf < 2; mf++) {
        int t0 = wm + mf * 16 + gid;
        int tok0 = b * SEQ + c * CHUNK + t0;
        float i0 = den_sm[t0], i1 = den_sm[t0 + 8];
        #pragma unroll
        for (int nf = 0; nf < 8; nf++) {
            int m0 = nf * 8 + tig * 2;
            *(__half2*)(g_ctx_h + (size_t)tok0 * DM + h * DH + m0) =
                __floats2half2_rn(c2[mf][nf][0] * i0, c2[mf][nf][1] * i0);
            *(__half2*)(g_ctx_h + (size_t)(tok0 + 8) * DM + h * DH + m0) =
                __floats2half2_rn(c2[mf][nf][2] * i1, c2[mf][nf][3] * i1);
        }
    }
}

// ---------------- launch ----------------
extern "C" void kernel_launch(void* const* d_in, const int* in_sizes, int n_in,
                              void* d_out, int out_size) {
    const float* x      = (const float*)d_in[0];
    const float* ln_g   = (const float*)d_in[1];
    const float* ln_b   = (const float*)d_in[2];
    const float* w_qkv  = (const float*)d_in[3];
    const float* b_qkv  = (const float*)d_in[4];
    const float* w_gate = (const float*)d_in[5];
    const float* b_gate = (const float*)d_in[6];
    const float* w_proj = (const float*)d_in[7];
    const float* b_proj = (const float*)d_in[8];
    float* out = (float*)d_out;

    void *p_xnorm, *p_xr, *p_ctx, *p_wqkv, *p_wgate, *p_wproj;
    cudaGetSymbolAddress(&p_xnorm, g_xnorm_h);
    cudaGetSymbolAddress(&p_xr,    g_xr_h);
    cudaGetSymbolAddress(&p_ctx,   g_ctx_h);
    cudaGetSymbolAddress(&p_wqkv,  g_wqkv_h);
    cudaGetSymbolAddress(&p_wgate, g_wgate_h);
    cudaGetSymbolAddress(&p_wproj, g_wproj_h);

    cudaFuncSetAttribute(passC_kernel, cudaFuncAttributeMaxDynamicSharedMemorySize, PC_SMEM);
    cudaFuncSetAttribute(passA_kernel, cudaFuncAttributeMaxDynamicSharedMemorySize, PA_SMEM);
    cudaFuncSetAttribute(mma_gemm_dual,   cudaFuncAttributeMaxDynamicSharedMemorySize, GEMM_SMEM_BYTES);
    cudaFuncSetAttribute(mma_gemm_single, cudaFuncAttributeMaxDynamicSharedMemorySize, GEMM_SMEM_BYTES);

    // 0+1. prep: LayerNorm + weight transpose
    prep_kernel<<<NTOK + 160 * 32, 256>>>(x, ln_g, ln_b, w_qkv, w_gate, w_proj);
    // 2+3. persistent dual GEMM (BK=64)
    mma_gemm_dual<<<296, 128, GEMM_SMEM_BYTES>>>(
        (const __half*)p_xnorm, (const __half*)p_wqkv, b_qkv,
        (const __half*)p_xr,    (const __half*)p_wgate, b_gate);
    // 4+5. fused gate-normalize + split + elu+1
    gatesplit_kernel<<<NTOK, 256>>>();
    // 6-8. chunked causal linear attention (tensor-core, trans-ldmatrix)
    passA_kernel<<<NBH * NCH, 128, PA_SMEM>>>();
    passB_kernel<<<dim3(16, NBH), 256>>>();
    passC_kernel<<<NBH * NCH, 128, PC_SMEM>>>();
    // 9. projection (BK=64)
    mma_gemm_single<<<dim3(DM / 128, NTOK / 128), 128, GEMM_SMEM_BYTES>>>(
        (const __half*)p_ctx, (const __half*)p_wproj, b_proj, out);
}